// round 13
// baseline (speedup 1.0000x reference)
#include <cuda_runtime.h>
#include <cuda_fp16.h>
#include <cstdint>

// Fixed-shape problem: G=4000, B=8, DEG=32, BATCH=128
#define G_     4000
#define NB_    132000               // G*DEG + G
#define BATCH_ 128
#define D_     32000
#define CAP    128                  // per-group bin capacity (max cnt ~60)
#define CHUNK  3                    // block-pairs per pipeline chunk
#define NBUF   3                    // rotating chunk buffers
#define SXS    136                  // sx row stride in halves (272B: conflict-free ldmatrix)
#define STG_HALVES (16 * SXS)       // 2176 halves per pair tile
#define STG_BYTES  (STG_HALVES * 2) // 4352 B per pair tile
#define SCAT_CTAS ((NB_ + 1023) / 1024)

// Scratch (no allocations allowed -> __device__ globals; zero-init on load)
__device__ int    g_cnt[G_];                      // re-zeroed by main_kernel each run
__device__ int2   g_bin[(size_t)G_ * CAP];        // (block id n, src group)
__device__ __half g_xTh[(size_t)D_ * BATCH_];     // fp16 xT[col * 128 + b]

// ---------------- fused pre-kernel: transpose (CTAs 0..3999) + bin scatter ----------

__global__ void __launch_bounds__(256) pre_kernel(const float* __restrict__ x,
                                                  const int* __restrict__ bi,
                                                  const int* __restrict__ bo) {
    int bid = blockIdx.x;
    if (bid < 4000) {
        __shared__ float tile[32][33];
        int bx = bid % 1000, by = bid / 1000;
        int c0 = bx * 32;             // along D
        int r0 = by * 32;             // along BATCH
        int tx = threadIdx.x & 31, ty = threadIdx.x >> 5;
#pragma unroll
        for (int r = 0; r < 4; r++)
            tile[ty + 8 * r][tx] = x[(size_t)(r0 + ty + 8 * r) * D_ + (c0 + tx)];
        __syncthreads();
        int t = threadIdx.x;
        int d = t >> 3;
        int bq = (t & 7) * 4;
        __half h[4];
#pragma unroll
        for (int k = 0; k < 4; k++) h[k] = __float2half_rn(tile[bq + k][d]);
        *(uint2*)&g_xTh[(size_t)(c0 + d) * BATCH_ + r0 + bq] = *(const uint2*)h;
    } else {
        int i0 = ((bid - 4000) * 256 + threadIdx.x) * 4;
        if (i0 >= NB_) return;
        int4 vin  = *(const int4*)(bi + i0);
        int4 vout = *(const int4*)(bo + i0);
#pragma unroll
        for (int k = 0; k < 4; k++) {
            int src = (&vin.x)[k];
            int dst = (&vout.x)[k];
            int p = atomicAdd(&g_cnt[dst], 1);
            g_bin[(size_t)dst * CAP + p] = make_int2(i0 + k, src);
        }
    }
}

// ---------------- tensor-core main: chunked triple-buffered cp.async pipeline -------

__device__ __forceinline__ void ldsm4t(uint32_t& r0, uint32_t& r1, uint32_t& r2,
                                       uint32_t& r3, uint32_t addr) {
    asm volatile("ldmatrix.sync.aligned.m8n8.x4.trans.shared.b16 {%0,%1,%2,%3}, [%4];"
                 : "=r"(r0), "=r"(r1), "=r"(r2), "=r"(r3) : "r"(addr));
}

__device__ __forceinline__ void mma16816(float* c, uint32_t a0, uint32_t a1, uint32_t a2,
                                         uint32_t a3, uint32_t b0, uint32_t b1) {
    asm volatile("mma.sync.aligned.m16n8k16.row.col.f32.f16.f16.f32 "
                 "{%0,%1,%2,%3}, {%4,%5,%6,%7}, {%8,%9}, {%0,%1,%2,%3};"
                 : "+f"(c[0]), "+f"(c[1]), "+f"(c[2]), "+f"(c[3])
                 : "r"(a0), "r"(a1), "r"(a2), "r"(a3), "r"(b0), "r"(b1));
}

__device__ __forceinline__ void cp16(uint32_t saddr, const void* gaddr) {
    asm volatile("cp.async.cg.shared.global [%0], [%1], 16;"
                 :: "r"(saddr), "l"(gaddr) : "memory");
}
__device__ __forceinline__ void cp_commit() {
    asm volatile("cp.async.commit_group;" ::: "memory");
}
template <int N>
__device__ __forceinline__ void cp_wait() {
    asm volatile("cp.async.wait_group %0;" :: "n"(N) : "memory");
}

__device__ __forceinline__ uint32_t packh2(float lo, float hi) {
    __half2 h = __halves2half2(__float2half_rn(lo), __float2half_rn(hi));
    return *(uint32_t*)&h;
}

__global__ void __launch_bounds__(128) main_kernel(const float* __restrict__ x,
                                                   const float* __restrict__ w,
                                                   float* __restrict__ out) {
    __shared__ __align__(16) __half sx[NBUF * CHUNK * STG_HALVES];  // 39168 B (aliased as sred)
    __shared__ int ssrc[CAP];   // src group per block
    __shared__ int snum[CAP];   // block id n per block

    int g = blockIdx.x;
    int tid = threadIdx.x, lane = tid & 31, wid = tid >> 5;
    int cnt = g_cnt[g];
    const int2* bin = g_bin + (size_t)g * CAP;

    if (tid < cnt) {
        int2 e = bin[tid];
        snum[tid] = e.x;
        ssrc[tid] = e.y;
    }
    __syncthreads();

    int npairs = (cnt + 1) >> 1;
    int nchunks = (npairs + CHUNK - 1) / CHUNK;

    uint32_t sx_u;
    asm("{ .reg .u64 t; cvta.to.shared.u64 t, %1; cvt.u32.u64 %0, t; }" : "=r"(sx_u) : "l"(sx));

    // per-thread constants
    int kk  = tid >> 4;            // copy row 0..7
    int col = (tid & 15) * 8;      // copy column (halves)
    int gr  = lane >> 2;           // A frag: o row
    int c2  = (lane & 3) << 1;     // A frag: i col pair base
    int r8  = lane & 7, t4 = lane >> 3;
    uint32_t baddr_off = ((uint32_t)(r8 + ((t4 & 1) << 3)) * SXS
                          + (uint32_t)(wid * 32 + ((t4 >> 1) << 3))) * 2;
    uint32_t cpoff = (uint32_t)(kk * SXS + col) * 2;

    float acc[4][4];
#pragma unroll
    for (int q = 0; q < 4; q++)
#pragma unroll
        for (int r = 0; r < 4; r++) acc[q][r] = 0.f;

    // ---- prologue: issue chunk 0 into buffer 0 ----
#pragma unroll
    for (int jp = 0; jp < CHUNK; jp++) {
        int p = jp;
        if (p < npairs) {
            int j0 = 2 * p;
            int s0 = ssrc[j0];
            int s1 = (j0 + 1 < cnt) ? ssrc[j0 + 1] : s0;
            uint32_t d = sx_u + jp * STG_BYTES + cpoff;
            cp16(d,               g_xTh + ((size_t)s0 * 8 + kk) * BATCH_ + col);
            cp16(d + 8 * SXS * 2, g_xTh + ((size_t)s1 * 8 + kk) * BATCH_ + col);
        }
    }
    cp_commit();

    const uint32_t zero = 0;
    for (int c = 0; c < nchunks; c++) {
        // 1) issue chunk c+1 into buffer (c+1)%NBUF (safe: its last readers,
        //    chunk c-2, finished before the iteration-(c-1) barrier)
        {
            int cb = ((c + 1) % NBUF) * CHUNK;
#pragma unroll
            for (int jp = 0; jp < CHUNK; jp++) {
                int p = (c + 1) * CHUNK + jp;
                if (p < npairs) {
                    int j0 = 2 * p;
                    int s0 = ssrc[j0];
                    int s1 = (j0 + 1 < cnt) ? ssrc[j0 + 1] : s0;
                    uint32_t d = sx_u + (cb + jp) * STG_BYTES + cpoff;
                    cp16(d,               g_xTh + ((size_t)s0 * 8 + kk) * BATCH_ + col);
                    cp16(d + 8 * SXS * 2, g_xTh + ((size_t)s1 * 8 + kk) * BATCH_ + col);
                }
            }
            cp_commit();
        }

        // 2) prefetch A fragments for the whole chunk c (LDGs fly during wait+bar)
        uint32_t a0r[CHUNK], a2r[CHUNK];
#pragma unroll
        for (int jp = 0; jp < CHUNK; jp++) {
            int p = c * CHUNK + jp;
            a0r[jp] = 0; a2r[jp] = 0;
            if (p < npairs) {
                const float* wp = w + (size_t)snum[2 * p] * 64 + c2 * 8 + gr;
                a0r[jp] = packh2(wp[0], wp[8]);
                if (2 * p + 1 < cnt) {
                    const float* wq = w + (size_t)snum[2 * p + 1] * 64 + c2 * 8 + gr;
                    a2r[jp] = packh2(wq[0], wq[8]);
                }
            }
        }

        cp_wait<1>();        // chunk c's group complete (c+1 still in flight)
        __syncthreads();     // one barrier per chunk

        // 3) compute chunk c: 3 pairs back-to-back
        int cb = (c % NBUF) * CHUNK;
#pragma unroll
        for (int jp = 0; jp < CHUNK; jp++) {
            int p = c * CHUNK + jp;
            if (p < npairs) {
                uint32_t addr = sx_u + (cb + jp) * STG_BYTES + baddr_off;
                uint32_t b00, b01, b10, b11, b20, b21, b30, b31;
                ldsm4t(b00, b01, b10, b11, addr);
                ldsm4t(b20, b21, b30, b31, addr + 32);
                mma16816(acc[0], a0r[jp], zero, a2r[jp], zero, b00, b01);
                mma16816(acc[1], a0r[jp], zero, a2r[jp], zero, b10, b11);
                mma16816(acc[2], a0r[jp], zero, a2r[jp], zero, b20, b21);
                mma16816(acc[3], a0r[jp], zero, a2r[jp], zero, b30, b31);
            }
        }
    }

    // ---- epilogue: frags -> smem [8 o][132 b], residual, coalesced store ----
    __syncthreads();
    float* sred = (float*)sx;   // 8*132*4 = 4224 B
#pragma unroll
    for (int q = 0; q < 4; q++) {
        int o = lane >> 2;
        int b = wid * 32 + q * 8 + ((lane & 3) << 1);
        sred[o * 132 + b]     = acc[q][0];
        sred[o * 132 + b + 1] = acc[q][1];
    }
    __syncthreads();

    if (tid == 0) g_cnt[g] = 0;   // ready for next graph replay

    int b = tid;
    size_t obase = (size_t)b * D_ + (size_t)g * 8;
    float4 r0 = *(const float4*)(x + obase);
    float4 r1 = *(const float4*)(x + obase + 4);
    float s[8];
#pragma unroll
    for (int o = 0; o < 8; o++) s[o] = sred[o * 132 + b];
    float4 o0 = make_float4(r0.x + s[0], r0.y + s[1], r0.z + s[2], r0.w + s[3]);
    float4 o1 = make_float4(r1.x + s[4], r1.y + s[5], r1.z + s[6], r1.w + s[7]);
    *(float4*)(out + obase)     = o0;
    *(float4*)(out + obase + 4) = o1;
}

// ---------------- launch ----------------

extern "C" void kernel_launch(void* const* d_in, const int* in_sizes, int n_in,
                              void* d_out, int out_size) {
    const float* x  = (const float*)d_in[0];   // (128, 32000) f32
    const float* w  = (const float*)d_in[1];   // (132000, 8, 8) f32
    const int*   bi = (const int*)d_in[2];     // block_in
    const int*   bo = (const int*)d_in[3];     // block_out
    float* out = (float*)d_out;

    pre_kernel<<<4000 + SCAT_CTAS, 256>>>(x, bi, bo);
    main_kernel<<<G_, 128>>>(x, w, out);
}

// round 14
// speedup vs baseline: 1.0056x; 1.0056x over previous
#include <cuda_runtime.h>
#include <cuda_fp16.h>
#include <cstdint>

// Fixed-shape problem: G=4000, B=8, DEG=32, BATCH=128
#define G_     4000
#define NB_    132000               // G*DEG + G
#define BATCH_ 128
#define D_     32000
#define CAP    128                  // per-group bin capacity (max cnt ~60)
#define NSTG   5                    // per-warp cp.async pipeline depth (pairs)
#define ROWB   80                   // bytes per row in warp tile (16 rows x 64B data, pad->80)
#define STGB   (16 * ROWB)          // 1280 B per stage per warp
#define WBUF   (NSTG * STGB)        // 6400 B per warp
#define SCAT_CTAS  ((NB_ + 1023) / 1024)          // 129
#define WCONV_CTAS (NB_ / 32)                     // 4125 (32 blocks per CTA)

// Scratch (no allocations allowed -> __device__ globals; zero-init on load)
__device__ int    g_cnt[G_];                      // re-zeroed by main_kernel each run
__device__ int2   g_bin[(size_t)G_ * CAP];        // (block id n, src group)
__device__ __half g_xTh[(size_t)D_ * BATCH_];     // fp16 xT[col * 128 + b]
__device__ __half g_wT[(size_t)NB_ * 64];         // fp16 w transposed: [n][o][i]

// ------------- fused pre-kernel: transpose | bin scatter | w fp16-transpose -------------

__global__ void __launch_bounds__(256) pre_kernel(const float* __restrict__ x,
                                                  const float* __restrict__ w,
                                                  const int* __restrict__ bi,
                                                  const int* __restrict__ bo) {
    int bid = blockIdx.x;
    if (bid < 4000) {
        // ---- transpose x (BATCH, D) -> fp16 xT (D, BATCH) ----
        __shared__ float tile[32][33];
        int bx = bid % 1000, by = bid / 1000;
        int c0 = bx * 32;             // along D
        int r0 = by * 32;             // along BATCH
        int tx = threadIdx.x & 31, ty = threadIdx.x >> 5;
#pragma unroll
        for (int r = 0; r < 4; r++)
            tile[ty + 8 * r][tx] = x[(size_t)(r0 + ty + 8 * r) * D_ + (c0 + tx)];
        __syncthreads();
        int t = threadIdx.x;
        int d = t >> 3;
        int bq = (t & 7) * 4;
        __half h[4];
#pragma unroll
        for (int k = 0; k < 4; k++) h[k] = __float2half_rn(tile[bq + k][d]);
        *(uint2*)&g_xTh[(size_t)(c0 + d) * BATCH_ + r0 + bq] = *(const uint2*)h;
    } else if (bid < 4000 + SCAT_CTAS) {
        // ---- direct bin scatter ----
        int i0 = ((bid - 4000) * 256 + threadIdx.x) * 4;
        if (i0 >= NB_) return;
        int4 vin  = *(const int4*)(bi + i0);
        int4 vout = *(const int4*)(bo + i0);
#pragma unroll
        for (int k = 0; k < 4; k++) {
            int src = (&vin.x)[k];
            int dst = (&vout.x)[k];
            int p = atomicAdd(&g_cnt[dst], 1);
            g_bin[(size_t)dst * CAP + p] = make_int2(i0 + k, src);
        }
    } else {
        // ---- w f32 [n][i][o] -> fp16 [n][o][i], 32 blocks per CTA ----
        __shared__ float swc[32 * 64];
        int n0 = (bid - 4000 - SCAT_CTAS) * 32;
        int t = threadIdx.x;
        for (int idx = t; idx < 32 * 64; idx += 256)
            swc[idx] = w[(size_t)n0 * 64 + idx];
        __syncthreads();
        int nl = t >> 3, o = t & 7;
        __half h[8];
#pragma unroll
        for (int i = 0; i < 8; i++)
            h[i] = __float2half_rn(swc[nl * 64 + i * 8 + o]);
        *(uint4*)&g_wT[(size_t)(n0 + nl) * 64 + o * 8] = *(const uint4*)h;
    }
}

// ---------------- tensor-core main: warp-private cp.async pipelines ----------------

__device__ __forceinline__ void ldsm4t(uint32_t& r0, uint32_t& r1, uint32_t& r2,
                                       uint32_t& r3, uint32_t addr) {
    asm volatile("ldmatrix.sync.aligned.m8n8.x4.trans.shared.b16 {%0,%1,%2,%3}, [%4];"
                 : "=r"(r0), "=r"(r1), "=r"(r2), "=r"(r3) : "r"(addr));
}

__device__ __forceinline__ void mma16816(float* c, uint32_t a0, uint32_t a1, uint32_t a2,
                                         uint32_t a3, uint32_t b0, uint32_t b1) {
    asm volatile("mma.sync.aligned.m16n8k16.row.col.f32.f16.f16.f32 "
                 "{%0,%1,%2,%3}, {%4,%5,%6,%7}, {%8,%9}, {%0,%1,%2,%3};"
                 : "+f"(c[0]), "+f"(c[1]), "+f"(c[2]), "+f"(c[3])
                 : "r"(a0), "r"(a1), "r"(a2), "r"(a3), "r"(b0), "r"(b1));
}

__device__ __forceinline__ void cp16(uint32_t saddr, const void* gaddr) {
    asm volatile("cp.async.cg.shared.global [%0], [%1], 16;"
                 :: "r"(saddr), "l"(gaddr) : "memory");
}
__device__ __forceinline__ void cp_commit() {
    asm volatile("cp.async.commit_group;" ::: "memory");
}
template <int N>
__device__ __forceinline__ void cp_wait() {
    asm volatile("cp.async.wait_group %0;" :: "n"(N) : "memory");
}

__global__ void __launch_bounds__(128) main_kernel(const float* __restrict__ x,
                                                   float* __restrict__ out) {
    __shared__ __align__(16) __half sx[4 * WBUF / 2];   // 25600 B (aliased as sred)
    __shared__ int ssrc[CAP];   // src group per block
    __shared__ int snum[CAP];   // block id n per block

    int g = blockIdx.x;
    int tid = threadIdx.x, lane = tid & 31, wid = tid >> 5;
    int cnt = g_cnt[g];
    const int2* bin = g_bin + (size_t)g * CAP;

    if (tid < cnt) {
        int2 e = bin[tid];
        snum[tid] = e.x;
        ssrc[tid] = e.y;
    }
    __syncthreads();

    int npairs = (cnt + 1) >> 1;

    uint32_t sx_u;
    asm("{ .reg .u64 t; cvta.to.shared.u64 t, %1; cvt.u32.u64 %0, t; }" : "=r"(sx_u) : "l"(sx));
    uint32_t wbase = sx_u + wid * WBUF;

    // per-lane constants
    int row1 = lane >> 2;                 // copy row within block tile (0..7)
    int quad = lane & 3;                  // 16B chunk within 64B warp row-slice
    uint32_t cpoff = (uint32_t)(row1 * ROWB + quad * 16);
    int gcol = wid * 32 + quad * 8;       // gmem column (halves)
    int r8 = lane & 7, t4 = lane >> 3;
    uint32_t boff = (uint32_t)((r8 + ((t4 & 1) << 3)) * ROWB + ((t4 >> 1) << 4));
    int aoff = (lane >> 2) * 8 + ((lane & 3) << 1);   // g_wT offset: o*8 + i

    float acc[4][4];
#pragma unroll
    for (int q = 0; q < 4; q++)
#pragma unroll
        for (int r = 0; r < 4; r++) acc[q][r] = 0.f;

    // ---- prologue: fill the per-warp pipeline (always NSTG commits) ----
#pragma unroll
    for (int s = 0; s < NSTG; s++) {
        if (s < npairs) {
            int j0 = 2 * s;
            int s0 = ssrc[j0];
            int s1 = (j0 + 1 < cnt) ? ssrc[j0 + 1] : s0;
            uint32_t d = wbase + s * STGB + cpoff;
            cp16(d,            g_xTh + ((size_t)s0 * 8 + row1) * BATCH_ + gcol);
            cp16(d + 8 * ROWB, g_xTh + ((size_t)s1 * 8 + row1) * BATCH_ + gcol);
        }
        cp_commit();
    }

    // ---- A regs for pair 0 (one LDG.32 per block from fp16 wT) ----
    uint32_t ca0 = 0, ca2 = 0;
    {
        ca0 = *(const uint32_t*)(g_wT + (size_t)snum[0] * 64 + aoff);
        if (1 < cnt)
            ca2 = *(const uint32_t*)(g_wT + (size_t)snum[1] * 64 + aoff);
    }

    const uint32_t zero = 0;
    int st = 0;
    for (int p = 0; p < npairs; p++) {
        // prefetch A for pair p+1 (flies under the wait + mma)
        uint32_t na0 = 0, na2 = 0;
        int pn = p + 1;
        if (pn < npairs) {
            na0 = *(const uint32_t*)(g_wT + (size_t)snum[2 * pn] * 64 + aoff);
            if (2 * pn + 1 < cnt)
                na2 = *(const uint32_t*)(g_wT + (size_t)snum[2 * pn + 1] * 64 + aoff);
        }

        cp_wait<NSTG - 1>();   // this warp's group p complete
        __syncwarp();

        uint32_t addr = wbase + st * STGB + boff;
        uint32_t b00, b01, b10, b11, b20, b21, b30, b31;
        ldsm4t(b00, b01, b10, b11, addr);
        ldsm4t(b20, b21, b30, b31, addr + 32);
        mma16816(acc[0], ca0, zero, ca2, zero, b00, b01);
        mma16816(acc[1], ca0, zero, ca2, zero, b10, b11);
        mma16816(acc[2], ca0, zero, ca2, zero, b20, b21);
        mma16816(acc[3], ca0, zero, ca2, zero, b30, b31);

        // refill stage st with pair p+NSTG (same-warp readers already consumed it)
        int pf = p + NSTG;
        if (pf < npairs) {
            int j0 = 2 * pf;
            int s0 = ssrc[j0];
            int s1 = (j0 + 1 < cnt) ? ssrc[j0 + 1] : s0;
            uint32_t d = wbase + st * STGB + cpoff;
            cp16(d,            g_xTh + ((size_t)s0 * 8 + row1) * BATCH_ + gcol);
            cp16(d + 8 * ROWB, g_xTh + ((size_t)s1 * 8 + row1) * BATCH_ + gcol);
        }
        cp_commit();

        ca0 = na0; ca2 = na2;
        st = (st + 1 == NSTG) ? 0 : st + 1;
    }

    // ---- epilogue: frags -> smem [8 o][132 b], residual, coalesced store ----
    __syncthreads();
    float* sred = (float*)sx;   // 8*132*4 = 4224 B
#pragma unroll
    for (int q = 0; q < 4; q++) {
        int o = lane >> 2;
        int b = wid * 32 + q * 8 + ((lane & 3) << 1);
        sred[o * 132 + b]     = acc[q][0];
        sred[o * 132 + b + 1] = acc[q][1];
    }
    __syncthreads();

    if (tid == 0) g_cnt[g] = 0;   // ready for next graph replay

    int b = tid;
    size_t obase = (size_t)b * D_ + (size_t)g * 8;
    float4 r0 = *(const float4*)(x + obase);
    float4 r1 = *(const float4*)(x + obase + 4);
    float s[8];
#pragma unroll
    for (int o = 0; o < 8; o++) s[o] = sred[o * 132 + b];
    float4 o0 = make_float4(r0.x + s[0], r0.y + s[1], r0.z + s[2], r0.w + s[3]);
    float4 o1 = make_float4(r1.x + s[4], r1.y + s[5], r1.z + s[6], r1.w + s[7]);
    *(float4*)(out + obase)     = o0;
    *(float4*)(out + obase + 4) = o1;
}

// ---------------- launch ----------------

extern "C" void kernel_launch(void* const* d_in, const int* in_sizes, int n_in,
                              void* d_out, int out_size) {
    const float* x  = (const float*)d_in[0];   // (128, 32000) f32
    const float* w  = (const float*)d_in[1];   // (132000, 8, 8) f32
    const int*   bi = (const int*)d_in[2];     // block_in
    const int*   bo = (const int*)d_in[3];     // block_out
    float* out = (float*)d_out;

    pre_kernel<<<4000 + SCAT_CTAS + WCONV_CTAS, 256>>>(x, w, bi, bo);
    main_kernel<<<G_, 128>>>(x, out);
}

// round 15
// speedup vs baseline: 1.1560x; 1.1495x over previous
#include <cuda_runtime.h>
#include <cuda_fp16.h>
#include <cstdint>

// Fixed-shape problem: G=4000, B=8, DEG=32, BATCH=128
#define G_     4000
#define NB_    132000               // G*DEG + G
#define BATCH_ 128
#define D_     32000
#define CAP    128                  // per-group bin capacity (max cnt ~60)
#define NSTG   4                    // per-warp cp.async pipeline depth (pairs)
#define ROWB   80                   // bytes per row in warp tile (64B data + 16B pad)
#define STGB   (16 * ROWB)          // 1280 B per stage per warp
#define WBUF   (NSTG * STGB)        // 5120 B per warp
#define SCAT_CTAS ((NB_ + 255) / 256)    // 516 (1 element per thread)

// Scratch (no allocations allowed -> __device__ globals; zero-init on load)
__device__ int    g_cnt[G_];                      // re-zeroed by main_kernel each run
__device__ int2   g_bin[(size_t)G_ * CAP];        // (block id n, src group)
__device__ __half g_xTh[(size_t)D_ * BATCH_];     // fp16 xT[col * 128 + b]

// ---------------- fused pre-kernel: transpose (CTAs 0..3999) + bin scatter ----------

__global__ void __launch_bounds__(256) pre_kernel(const float* __restrict__ x,
                                                  const int* __restrict__ bi,
                                                  const int* __restrict__ bo) {
    int bid = blockIdx.x;
    if (bid < 4000) {
        // ---- transpose x (BATCH, D) -> fp16 xT (D, BATCH) ----
        __shared__ float tile[32][33];
        int bx = bid % 1000, by = bid / 1000;
        int c0 = bx * 32;             // along D
        int r0 = by * 32;             // along BATCH
        int tx = threadIdx.x & 31, ty = threadIdx.x >> 5;
#pragma unroll
        for (int r = 0; r < 4; r++)
            tile[ty + 8 * r][tx] = x[(size_t)(r0 + ty + 8 * r) * D_ + (c0 + tx)];
        __syncthreads();
        int t = threadIdx.x;
        int d = t >> 3;
        int bq = (t & 7) * 4;
        __half h[4];
#pragma unroll
        for (int k = 0; k < 4; k++) h[k] = __float2half_rn(tile[bq + k][d]);
        *(uint2*)&g_xTh[(size_t)(c0 + d) * BATCH_ + r0 + bq] = *(const uint2*)h;
    } else {
        // ---- direct bin scatter: 1 element per thread ----
        int i = (bid - 4000) * 256 + threadIdx.x;
        if (i >= NB_) return;
        int src = bi[i];
        int dst = bo[i];
        int p = atomicAdd(&g_cnt[dst], 1);
        g_bin[(size_t)dst * CAP + p] = make_int2(i, src);
    }
}

// ---------------- tensor-core main: warp-private cp.async pipelines ----------------

__device__ __forceinline__ void ldsm4t(uint32_t& r0, uint32_t& r1, uint32_t& r2,
                                       uint32_t& r3, uint32_t addr) {
    asm volatile("ldmatrix.sync.aligned.m8n8.x4.trans.shared.b16 {%0,%1,%2,%3}, [%4];"
                 : "=r"(r0), "=r"(r1), "=r"(r2), "=r"(r3) : "r"(addr));
}

__device__ __forceinline__ void mma16816(float* c, uint32_t a0, uint32_t a1, uint32_t a2,
                                         uint32_t a3, uint32_t b0, uint32_t b1) {
    asm volatile("mma.sync.aligned.m16n8k16.row.col.f32.f16.f16.f32 "
                 "{%0,%1,%2,%3}, {%4,%5,%6,%7}, {%8,%9}, {%0,%1,%2,%3};"
                 : "+f"(c[0]), "+f"(c[1]), "+f"(c[2]), "+f"(c[3])
                 : "r"(a0), "r"(a1), "r"(a2), "r"(a3), "r"(b0), "r"(b1));
}

__device__ __forceinline__ void cp16(uint32_t saddr, const void* gaddr) {
    asm volatile("cp.async.cg.shared.global [%0], [%1], 16;"
                 :: "r"(saddr), "l"(gaddr) : "memory");
}
__device__ __forceinline__ void cp_commit() {
    asm volatile("cp.async.commit_group;" ::: "memory");
}
template <int N>
__device__ __forceinline__ void cp_wait() {
    asm volatile("cp.async.wait_group %0;" :: "n"(N) : "memory");
}

__device__ __forceinline__ uint32_t packh2(float lo, float hi) {
    __half2 h = __halves2half2(__float2half_rn(lo), __float2half_rn(hi));
    return *(uint32_t*)&h;
}

__global__ void __launch_bounds__(128, 9) main_kernel(const float* __restrict__ x,
                                                      const float* __restrict__ w,
                                                      float* __restrict__ out) {
    __shared__ __align__(16) __half sx[4 * WBUF / 2];   // 20480 B (aliased as sred)
    __shared__ int ssrc[CAP];   // src group per block
    __shared__ int snum[CAP];   // block id n per block

    int g = blockIdx.x;
    int tid = threadIdx.x, lane = tid & 31, wid = tid >> 5;
    int cnt = g_cnt[g];
    const int2* bin = g_bin + (size_t)g * CAP;

    if (tid < cnt) {
        int2 e = bin[tid];
        snum[tid] = e.x;
        ssrc[tid] = e.y;
    }
    __syncthreads();

    int npairs = (cnt + 1) >> 1;

    uint32_t sx_u;
    asm("{ .reg .u64 t; cvta.to.shared.u64 t, %1; cvt.u32.u64 %0, t; }" : "=r"(sx_u) : "l"(sx));
    uint32_t wbase = sx_u + wid * WBUF;

    // per-lane constants
    int row1 = lane >> 2;                 // copy row within block tile (0..7)
    int quad = lane & 3;                  // 16B chunk within 64B warp row-slice
    uint32_t cpoff = (uint32_t)(row1 * ROWB + quad * 16);
    int gcol = wid * 32 + quad * 8;       // gmem column (halves)
    int r8 = lane & 7, t4 = lane >> 3;
    uint32_t boff = (uint32_t)((r8 + ((t4 & 1) << 3)) * ROWB + ((t4 >> 1) << 4));
    int gr = lane >> 2;                   // A frag: o row
    int c2 = (lane & 3) << 1;             // A frag: i col pair base

    float acc[4][4];
#pragma unroll
    for (int q = 0; q < 4; q++)
#pragma unroll
        for (int r = 0; r < 4; r++) acc[q][r] = 0.f;

    // ---- prologue: fill the per-warp pipeline (always NSTG commits) ----
#pragma unroll
    for (int s = 0; s < NSTG; s++) {
        if (s < npairs) {
            int j0 = 2 * s;
            int s0 = ssrc[j0];
            int s1 = (j0 + 1 < cnt) ? ssrc[j0 + 1] : s0;
            uint32_t d = wbase + s * STGB + cpoff;
            cp16(d,            g_xTh + ((size_t)s0 * 8 + row1) * BATCH_ + gcol);
            cp16(d + 8 * ROWB, g_xTh + ((size_t)s1 * 8 + row1) * BATCH_ + gcol);
        }
        cp_commit();
    }

    // ---- A regs for pair 0 (direct from f32 w: 2 LDG.32 + pack per block) ----
    uint32_t ca0 = 0, ca2 = 0;
    {
        const float* wp = w + (size_t)snum[0] * 64 + c2 * 8 + gr;
        ca0 = packh2(wp[0], wp[8]);
        if (1 < cnt) {
            const float* wq = w + (size_t)snum[1] * 64 + c2 * 8 + gr;
            ca2 = packh2(wq[0], wq[8]);
        }
    }

    const uint32_t zero = 0;
    int st = 0;
    for (int p = 0; p < npairs; p++) {
        // prefetch A for pair p+1 (LDGs fly under the wait + mma)
        uint32_t na0 = 0, na2 = 0;
        int pn = p + 1;
        if (pn < npairs) {
            const float* wp = w + (size_t)snum[2 * pn] * 64 + c2 * 8 + gr;
            na0 = packh2(wp[0], wp[8]);
            if (2 * pn + 1 < cnt) {
                const float* wq = w + (size_t)snum[2 * pn + 1] * 64 + c2 * 8 + gr;
                na2 = packh2(wq[0], wq[8]);
            }
        }

        cp_wait<NSTG - 1>();   // this warp's group p complete
        __syncwarp();

        uint32_t addr = wbase + st * STGB + boff;
        uint32_t b00, b01, b10, b11, b20, b21, b30, b31;
        ldsm4t(b00, b01, b10, b11, addr);
        ldsm4t(b20, b21, b30, b31, addr + 32);
        mma16816(acc[0], ca0, zero, ca2, zero, b00, b01);
        mma16816(acc[1], ca0, zero, ca2, zero, b10, b11);
        mma16816(acc[2], ca0, zero, ca2, zero, b20, b21);
        mma16816(acc[3], ca0, zero, ca2, zero, b30, b31);

        // refill stage st with pair p+NSTG (same-warp readers already consumed it)
        int pf = p + NSTG;
        if (pf < npairs) {
            int j0 = 2 * pf;
            int s0 = ssrc[j0];
            int s1 = (j0 + 1 < cnt) ? ssrc[j0 + 1] : s0;
            uint32_t d = wbase + st * STGB + cpoff;
            cp16(d,            g_xTh + ((size_t)s0 * 8 + row1) * BATCH_ + gcol);
            cp16(d + 8 * ROWB, g_xTh + ((size_t)s1 * 8 + row1) * BATCH_ + gcol);
        }
        cp_commit();

        ca0 = na0; ca2 = na2;
        st = (st + 1 == NSTG) ? 0 : st + 1;
    }

    // ---- epilogue: frags -> smem [8 o][132 b], residual, per-thread store ----
    __syncthreads();
    float* sred = (float*)sx;   // 8*132*4 = 4224 B
#pragma unroll
    for (int q = 0; q < 4; q++) {
        int o = lane >> 2;
        int b = wid * 32 + q * 8 + ((lane & 3) << 1);
        sred[o * 132 + b]     = acc[q][0];
        sred[o * 132 + b + 1] = acc[q][1];
    }
    __syncthreads();

    if (tid == 0) g_cnt[g] = 0;   // ready for next graph replay

    int b = tid;
    size_t obase = (size_t)b * D_ + (size_t)g * 8;
    float4 r0 = *(const float4*)(x + obase);
    float4 r1 = *(const float4*)(x + obase + 4);
    float s[8];
#pragma unroll
    for (int o = 0; o < 8; o++) s[o] = sred[o * 132 + b];
    float4 o0 = make_float4(r0.x + s[0], r0.y + s[1], r0.z + s[2], r0.w + s[3]);
    float4 o1 = make_float4(r1.x + s[4], r1.y + s[5], r1.z + s[6], r1.w + s[7]);
    *(float4*)(out + obase)     = o0;
    *(float4*)(out + obase + 4) = o1;
}

// ---------------- launch ----------------

extern "C" void kernel_launch(void* const* d_in, const int* in_sizes, int n_in,
                              void* d_out, int out_size) {
    const float* x  = (const float*)d_in[0];   // (128, 32000) f32
    const float* w  = (const float*)d_in[1];   // (132000, 8, 8) f32
    const int*   bi = (const int*)d_in[2];     // block_in
    const int*   bo = (const int*)d_in[3];     // block_out
    float* out = (float*)d_out;

    pre_kernel<<<4000 + SCAT_CTAS, 256>>>(x, bi, bo);
    main_kernel<<<G_, 128>>>(x, w, out);
}